// round 2
// baseline (speedup 1.0000x reference)
#include <cuda_runtime.h>
#include <math.h>

#define DEPTH  15
#define NNODES 65535      // 2^16 - 1
#define NEDGE  65534      // N - 1 (parent->child pairs)
#define HID    128
#define HEADS  4
#define NF     13
#define EFDIM  4
#define NL     3
#define EINW   (2*HID + EFDIM)   // 260

// ---------------- scratch (device globals; no allocs in kernel_launch) ----------------
__device__ float g_x13[NNODES * NF];                 // propagate result (N x 13)
__device__ float g_xA [NNODES * HID];                // node embedding ping
__device__ float g_xB [NNODES * HID];                // node embedding pong
__device__ float g_xp [NNODES * HEADS * HID];        // GAT projection / MLP hidden scratch (134 MB)
__device__ float g_es [NNODES * HEADS];              // attention src scores
__device__ float g_ed [NNODES * HEADS];              // attention dst scores
__device__ float g_ein[NEDGE * EINW];                // edge-MLP input / head hidden scratch

// ---------------- simple copy ----------------
__global__ void k_copy(const float* __restrict__ src, float* __restrict__ dst, int n) {
    int i = blockIdx.x * blockDim.x + threadIdx.x;
    if (i < n) dst[i] = src[i];
}

// ---------------- propagate: one level, x13[n] = 0.5*(x13[2n+1] + x13[2n+2]) ----------------
__global__ void k_prop(int start, int count) {
    int i = blockIdx.x * blockDim.x + threadIdx.x;
    if (i >= count * NF) return;
    int n = start + i / NF;
    int f = i - (i / NF) * NF;
    g_x13[n * NF + f] = 0.5f * (g_x13[(2 * n + 1) * NF + f] + g_x13[(2 * n + 2) * NF + f]);
}

// ---------------- tiled SGEMM with fused bias (+optional relu) ----------------
// C[M,Nn] = act(A[M,K] @ B[K,Nn] + bias). 64x64 tile, BK=16, 256 threads, 4x4/thread.
template <bool RELU>
__global__ void k_gemm(const float* __restrict__ A, const float* __restrict__ B,
                       const float* __restrict__ bias, float* __restrict__ C,
                       int M, int Nn, int K) {
    __shared__ float As[16][65];
    __shared__ float Bs[16][64];
    int tid = threadIdx.x;
    int tx = tid & 15, ty = tid >> 4;
    int rowBase = blockIdx.y * 64, colBase = blockIdx.x * 64;

    float acc[4][4];
#pragma unroll
    for (int i = 0; i < 4; i++)
#pragma unroll
        for (int j = 0; j < 4; j++) acc[i][j] = 0.f;

    for (int k0 = 0; k0 < K; k0 += 16) {
#pragma unroll
        for (int e = tid; e < 1024; e += 256) {
            int r = e >> 4, k = e & 15;
            int gr = rowBase + r, gk = k0 + k;
            As[k][r] = (gr < M && gk < K) ? A[(size_t)gr * K + gk] : 0.f;
        }
#pragma unroll
        for (int e = tid; e < 1024; e += 256) {
            int k = e >> 6, c = e & 63;
            int gk = k0 + k, gc = colBase + c;
            Bs[k][c] = (gk < K && gc < Nn) ? B[(size_t)gk * Nn + gc] : 0.f;
        }
        __syncthreads();
#pragma unroll
        for (int k = 0; k < 16; k++) {
            float a[4], b[4];
#pragma unroll
            for (int i = 0; i < 4; i++) a[i] = As[k][ty * 4 + i];
#pragma unroll
            for (int j = 0; j < 4; j++) b[j] = Bs[k][tx * 4 + j];
#pragma unroll
            for (int i = 0; i < 4; i++)
#pragma unroll
                for (int j = 0; j < 4; j++) acc[i][j] = fmaf(a[i], b[j], acc[i][j]);
        }
        __syncthreads();
    }
#pragma unroll
    for (int i = 0; i < 4; i++) {
        int r = rowBase + ty * 4 + i;
        if (r >= M) continue;
#pragma unroll
        for (int j = 0; j < 4; j++) {
            int c = colBase + tx * 4 + j;
            if (c >= Nn) continue;
            float v = acc[i][j] + (bias ? bias[c] : 0.f);
            if (RELU) v = fmaxf(v, 0.f);
            C[(size_t)r * Nn + c] = v;
        }
    }
}

// ---------------- attention scores: es/ed[n,h] = xp[n,h,:] . a_{src,dst}[h,:] ----------------
__global__ void k_attn(const float* __restrict__ asrc, const float* __restrict__ adst) {
    int gw   = (blockIdx.x * blockDim.x + threadIdx.x) >> 5;
    int lane = threadIdx.x & 31;
    if (gw >= NNODES * HEADS) return;
    int n = gw >> 2, h = gw & 3;
    const float* row = g_xp + (size_t)n * (HEADS * HID) + h * HID;
    const float* as  = asrc + h * HID;
    const float* ad  = adst + h * HID;
    float s = 0.f, d = 0.f;
    for (int k = lane; k < HID; k += 32) {
        float v = row[k];
        s = fmaf(v, as[k], s);
        d = fmaf(v, ad[k], d);
    }
#pragma unroll
    for (int o = 16; o > 0; o >>= 1) {
        s += __shfl_xor_sync(0xffffffffu, s, o);
        d += __shfl_xor_sync(0xffffffffu, d, o);
    }
    if (lane == 0) { g_es[gw] = s; g_ed[gw] = d; }
}

// ---------------- fused GAT: softmax over <=4 implicit neighbors + aggregate + mean
// ---------------- over heads + bias + residual + LayerNorm. One 128-thread block per node.
__global__ void k_gat(const float* __restrict__ xin, float* __restrict__ xout,
                      const float* __restrict__ gb, const float* __restrict__ lg,
                      const float* __restrict__ lb) {
    int n = blockIdx.x;
    int t = threadIdx.x;              // 0..127  == output dim
    int lane = t & 31, wid = t >> 5;

    __shared__ float alpha[HEADS][4];
    __shared__ int   nbs[4];
    __shared__ int   scnt;
    __shared__ float ws1[4], ws2[4];

    if (t == 0) {
        int c = 0; int nb[4];
        nb[c++] = n;                                   // self loop
        if (n > 0) nb[c++] = (n - 1) >> 1;             // parent
        int l = 2 * n + 1;
        if (l < NNODES) { nb[c++] = l; nb[c++] = l + 1; }  // children
        scnt = c;
#pragma unroll
        for (int i = 0; i < 4; i++) nbs[i] = (i < c) ? nb[i] : n;
    }
    __syncthreads();
    int cnt = scnt;

    if (t < HEADS) {
        float edv = g_ed[n * HEADS + t];
        float e[4]; float m = -1e30f;
        for (int j = 0; j < cnt; j++) {
            float v = g_es[nbs[j] * HEADS + t] + edv;
            v = (v >= 0.f) ? v : 0.2f * v;             // leaky_relu(0.2)
            e[j] = v; m = fmaxf(m, v);
        }
        float sum = 0.f;
        for (int j = 0; j < cnt; j++) { e[j] = expf(e[j] - m); sum += e[j]; }
        float inv = 1.f / sum;
#pragma unroll
        for (int j = 0; j < 4; j++) alpha[t][j] = (j < cnt) ? e[j] * inv : 0.f;
    }
    __syncthreads();

    float out = 0.f;
    for (int j = 0; j < cnt; j++) {
        const float* row = g_xp + (size_t)nbs[j] * (HEADS * HID);
#pragma unroll
        for (int h = 0; h < HEADS; h++) out = fmaf(alpha[h][j], row[h * HID + t], out);
    }
    float v = 0.25f * out + gb[t] + xin[(size_t)n * HID + t];  // mean over heads + bias + residual

    // LayerNorm over 128 dims
    float s = v;
#pragma unroll
    for (int o = 16; o > 0; o >>= 1) s += __shfl_xor_sync(0xffffffffu, s, o);
    if (lane == 0) ws1[wid] = s;
    __syncthreads();
    float mean = (ws1[0] + ws1[1] + ws1[2] + ws1[3]) * (1.f / HID);
    float dlt = v - mean;
    float s2 = dlt * dlt;
#pragma unroll
    for (int o = 16; o > 0; o >>= 1) s2 += __shfl_xor_sync(0xffffffffu, s2, o);
    if (lane == 0) ws2[wid] = s2;
    __syncthreads();
    float var = (ws2[0] + ws2[1] + ws2[2] + ws2[3]) * (1.f / HID);
    xout[(size_t)n * HID + t] = dlt * rsqrtf(var + 1e-5f) * lg[t] + lb[t];
}

// ---------------- build edge-MLP input rows: [x[e>>1], x[e+1], ef[e]] ----------------
__global__ void k_ein(const float* __restrict__ x, const float* __restrict__ ef) {
    int i = blockIdx.x * blockDim.x + threadIdx.x;
    if (i >= NEDGE * EINW) return;
    int e = i / EINW;
    int c = i - e * EINW;
    float v;
    if (c < HID)            v = x[(size_t)(e >> 1) * HID + c];
    else if (c < 2 * HID)   v = x[(size_t)(e + 1) * HID + (c - HID)];
    else                    v = ef[e * EFDIM + (c - 2 * HID)];
    g_ein[i] = v;
}

// ---------------- final head: logits[e,0:2] = H[e,:] @ W(128x2) + b ----------------
__global__ void k_out2(const float* __restrict__ H, const float* __restrict__ W,
                       const float* __restrict__ b, float* __restrict__ out) {
    int gw   = (blockIdx.x * blockDim.x + threadIdx.x) >> 5;
    int lane = threadIdx.x & 31;
    if (gw >= NEDGE) return;
    const float* h = H + (size_t)gw * HID;
    float s0 = 0.f, s1 = 0.f;
    for (int k = lane; k < HID; k += 32) {
        float hv = h[k];
        s0 = fmaf(hv, W[k * 2], s0);
        s1 = fmaf(hv, W[k * 2 + 1], s1);
    }
#pragma unroll
    for (int o = 16; o > 0; o >>= 1) {
        s0 += __shfl_xor_sync(0xffffffffu, s0, o);
        s1 += __shfl_xor_sync(0xffffffffu, s1, o);
    }
    if (lane == 0) {
        out[(size_t)gw * 2]     = s0 + b[0];
        out[(size_t)gw * 2 + 1] = s1 + b[1];
    }
}

// ---------------- launch ----------------
extern "C" void kernel_launch(void* const* d_in, const int* in_sizes, int n_in,
                              void* d_out, int out_size) {
    const float* nf    = (const float*)d_in[0];
    // d_in[1] = edge_index (tree is implicit), d_in[3] = is_leaf: both unused
    const float* ef    = (const float*)d_in[2];
    const float* npW1  = (const float*)d_in[4];
    const float* npb1  = (const float*)d_in[5];
    const float* npW2  = (const float*)d_in[6];
    const float* npb2  = (const float*)d_in[7];
    const float* gatW  = (const float*)d_in[8];
    const float* gatAs = (const float*)d_in[9];
    const float* gatAd = (const float*)d_in[10];
    const float* gatB  = (const float*)d_in[11];
    const float* lnG   = (const float*)d_in[12];
    const float* lnB   = (const float*)d_in[13];
    const float* emW1  = (const float*)d_in[14];
    const float* emb1  = (const float*)d_in[15];
    const float* emW2  = (const float*)d_in[16];
    const float* emb2  = (const float*)d_in[17];
    const float* whW1  = (const float*)d_in[18];
    const float* whb1  = (const float*)d_in[19];
    const float* whW2  = (const float*)d_in[20];
    const float* whb2  = (const float*)d_in[21];

    float* out    = (float*)d_out;
    float* embOut = out + (size_t)NEDGE * 2;   // output = [logits (E,2), emb (E,128)]

    float *x13, *xA, *xB, *xp, *ein;
    cudaGetSymbolAddress((void**)&x13, g_x13);
    cudaGetSymbolAddress((void**)&xA,  g_xA);
    cudaGetSymbolAddress((void**)&xB,  g_xB);
    cudaGetSymbolAddress((void**)&xp,  g_xp);
    cudaGetSymbolAddress((void**)&ein, g_ein);

    // 1) propagate: leaves hold features, internal = half-sum of children, bottom-up
    int n13 = NNODES * NF;
    k_copy<<<(n13 + 255) / 256, 256>>>(nf, x13, n13);
    for (int d = DEPTH - 1; d >= 0; d--) {
        int start = (1 << d) - 1, count = 1 << d;
        int tn = count * NF;
        k_prop<<<(tn + 255) / 256, 256>>>(start, count);
    }

    // 2) node MLP: x = relu(x13 @ W1 + b1) @ W2 + b2
    dim3 gN128(2, (NNODES + 63) / 64);
    k_gemm<true ><<<gN128, 256>>>(x13, npW1, npb1, xp, NNODES, HID, NF);
    k_gemm<false><<<gN128, 256>>>(xp,  npW2, npb2, xA, NNODES, HID, HID);

    // 3) GAT layers
    float* bufs[2] = {xA, xB};
    for (int l = 0; l < NL; l++) {
        float* xi = bufs[l & 1];
        float* xo = bufs[(l + 1) & 1];
        dim3 gN512(8, (NNODES + 63) / 64);
        k_gemm<false><<<gN512, 256>>>(xi, gatW + (size_t)l * HID * HEADS * HID,
                                      nullptr, xp, NNODES, HEADS * HID, HID);
        int nw = NNODES * HEADS;
        k_attn<<<(nw * 32 + 255) / 256, 256>>>(gatAs + (size_t)l * HEADS * HID,
                                               gatAd + (size_t)l * HEADS * HID);
        k_gat<<<NNODES, HID>>>(xi, xo, gatB + l * HID, lnG + l * HID, lnB + l * HID);
    }
    float* xf = bufs[NL & 1];   // final node embeddings (xB)

    // 4) edge MLP -> emb (written straight into output), then head -> logits
    int ne = NEDGE * EINW;
    k_ein<<<(ne + 255) / 256, 256>>>(xf, ef);
    dim3 gE128(2, (NEDGE + 63) / 64);
    k_gemm<true ><<<gE128, 256>>>(ein,    emW1, emb1, xp,     NEDGE, HID, EINW);
    k_gemm<false><<<gE128, 256>>>(xp,     emW2, emb2, embOut, NEDGE, HID, HID);
    k_gemm<true ><<<gE128, 256>>>(embOut, whW1, whb1, ein,    NEDGE, HID, HID);
    k_out2<<<(NEDGE * 32 + 255) / 256, 256>>>(ein, whW2, whb2, out);
}

// round 4
// speedup vs baseline: 1.5219x; 1.5219x over previous
#include <cuda_runtime.h>
#include <cuda_bf16.h>
#include <mma.h>
#include <cstdint>
#include <math.h>

using namespace nvcuda;

#define DEPTH  15
#define NNODES 65535
#define NEDGE  65534
#define MPAD   65536
#define HID    128
#define HEADS  4
#define NF     13
#define EFDIM  4
#define NL     3

// ---------------- scratch (device globals; zero-initialized; no allocs) ----------------
__device__ float g_x13[NNODES * NF];
__device__ float g_xA [MPAD * HID];
__device__ float g_xB [MPAD * HID];
__device__ float g_xp [MPAD * HEADS * HID];          // GEMM outputs (up to N=512)
__device__ float g_es [NNODES * HEADS];
__device__ float g_ed [NNODES * HEADS];
__device__ float g_wsd[HID * 8];                     // folded attention vectors
__device__ __nv_bfloat16 g_Ah [MPAD * HID];          // node-matrix split hi
__device__ __nv_bfloat16 g_Al [MPAD * HID];          // node-matrix split lo
__device__ __nv_bfloat16 g_Aeh[MPAD * 256];          // edge-matrix split hi (K=256)
__device__ __nv_bfloat16 g_Ael[MPAD * 256];          // edge-matrix split lo
__device__ __nv_bfloat16 g_Bh [512 * HID];           // weight split hi  [N][K]
__device__ __nv_bfloat16 g_Bl [512 * HID];           // weight split lo

// ---------------- split-precision conversion ----------------
__global__ void k_split(const float* __restrict__ x, __nv_bfloat16* __restrict__ hi,
                        __nv_bfloat16* __restrict__ lo, int n) {
    int i = blockIdx.x * blockDim.x + threadIdx.x;
    if (i >= n) return;
    float v = x[i];
    __nv_bfloat16 h = __float2bfloat16(v);
    hi[i] = h;
    lo[i] = __float2bfloat16(v - __bfloat162float(h));
}
// W[K,N] row-major -> bh/bl [N][K] (K contiguous)
__global__ void k_splitT(const float* __restrict__ W, __nv_bfloat16* __restrict__ bh,
                         __nv_bfloat16* __restrict__ bl, int K, int N) {
    int i = blockIdx.x * blockDim.x + threadIdx.x;
    if (i >= K * N) return;
    int k = i / N, n = i - k * N;
    float v = W[(size_t)k * N + n];
    __nv_bfloat16 h = __float2bfloat16(v);
    bh[(size_t)n * K + k] = h;
    bl[(size_t)n * K + k] = __float2bfloat16(v - __bfloat162float(h));
}

// ---------------- WMMA bf16x3 GEMM: C[128 x NT tile] = A[M,KC*128] @ B[Ntot,KC*128]^T ----
// A,B row-major bf16 (hi/lo). No bounds checks: A padded to 65536 rows, Ntot % NT == 0.
template <int NT, int KC>
__global__ void __launch_bounds__(256, 1)
k_mm(const __nv_bfloat16* __restrict__ Ah, const __nv_bfloat16* __restrict__ Al,
     const __nv_bfloat16* __restrict__ Bh, const __nv_bfloat16* __restrict__ Bl,
     float* __restrict__ C, int ldc) {
    extern __shared__ __nv_bfloat16 sm[];
    __nv_bfloat16* sAh = sm;
    __nv_bfloat16* sAl = sm + 128 * 136;
    __nv_bfloat16* sBh = sm + 2 * 128 * 136;
    __nv_bfloat16* sBl = sBh + NT * 136;

    const int tid = threadIdx.x;
    const int wid = tid >> 5;
    const int rowBase = blockIdx.x * 128;
    const int nBase   = blockIdx.y * NT;

    constexpr int FM = (NT == 256) ? 4 : 2;   // frags along M per warp
    constexpr int FN = 4;                     // frags along N per warp (64 cols)
    const int wm = (NT == 256) ? (wid & 1) : (wid & 3);
    const int wn = (NT == 256) ? (wid >> 1) : (wid >> 2);
    const int row_off = wm * (16 * FM);
    const int col_off = wn * 64;

    wmma::fragment<wmma::accumulator, 16, 16, 16, float> acc[FM][FN];
#pragma unroll
    for (int i = 0; i < FM; i++)
#pragma unroll
        for (int j = 0; j < FN; j++) wmma::fill_fragment(acc[i][j], 0.0f);

    const uint4* gAh = (const uint4*)Ah;
    const uint4* gAl = (const uint4*)Al;
    const uint4* gBh = (const uint4*)Bh;
    const uint4* gBl = (const uint4*)Bl;

    for (int c = 0; c < KC; c++) {
        // stage A chunk: 128 rows x 128 k (16 uint4 per row)
        for (int id = tid; id < 128 * 16; id += 256) {
            int r = id >> 4, q = id & 15;
            size_t g = (size_t)(rowBase + r) * (KC * 16) + c * 16 + q;
            *(uint4*)&sAh[r * 136 + q * 8] = gAh[g];
            *(uint4*)&sAl[r * 136 + q * 8] = gAl[g];
        }
        // stage B chunk: NT rows x 128 k
        for (int id = tid; id < NT * 16; id += 256) {
            int r = id >> 4, q = id & 15;
            size_t g = (size_t)(nBase + r) * (KC * 16) + c * 16 + q;
            *(uint4*)&sBh[r * 136 + q * 8] = gBh[g];
            *(uint4*)&sBl[r * 136 + q * 8] = gBl[g];
        }
        __syncthreads();

#pragma unroll
        for (int ks = 0; ks < 8; ks++) {
            wmma::fragment<wmma::matrix_a, 16, 16, 16, __nv_bfloat16, wmma::row_major> ah[FM], al[FM];
            wmma::fragment<wmma::matrix_b, 16, 16, 16, __nv_bfloat16, wmma::col_major> bh[FN], bl[FN];
#pragma unroll
            for (int i = 0; i < FM; i++) {
                wmma::load_matrix_sync(ah[i], sAh + (row_off + i * 16) * 136 + ks * 16, 136);
                wmma::load_matrix_sync(al[i], sAl + (row_off + i * 16) * 136 + ks * 16, 136);
            }
#pragma unroll
            for (int j = 0; j < FN; j++) {
                wmma::load_matrix_sync(bh[j], sBh + (col_off + j * 16) * 136 + ks * 16, 136);
                wmma::load_matrix_sync(bl[j], sBl + (col_off + j * 16) * 136 + ks * 16, 136);
            }
#pragma unroll
            for (int i = 0; i < FM; i++)
#pragma unroll
                for (int j = 0; j < FN; j++) {
                    wmma::mma_sync(acc[i][j], ah[i], bh[j], acc[i][j]);
                    wmma::mma_sync(acc[i][j], ah[i], bl[j], acc[i][j]);
                    wmma::mma_sync(acc[i][j], al[i], bh[j], acc[i][j]);
                }
        }
        __syncthreads();
    }

#pragma unroll
    for (int i = 0; i < FM; i++)
#pragma unroll
        for (int j = 0; j < FN; j++) {
            int r = rowBase + row_off + i * 16;
            int cc = nBase + col_off + j * 16;
            wmma::store_matrix_sync(C + (size_t)r * ldc + cc, acc[i][j], ldc, wmma::mem_row_major);
        }
}

// ---------------- misc ----------------
__global__ void k_copy(const float* __restrict__ src, float* __restrict__ dst, int n) {
    int i = blockIdx.x * blockDim.x + threadIdx.x;
    if (i < n) dst[i] = src[i];
}
__global__ void k_prop(int start, int count) {
    int i = blockIdx.x * blockDim.x + threadIdx.x;
    if (i >= count * NF) return;
    int n = start + i / NF;
    int f = i - (i / NF) * NF;
    g_x13[n * NF + f] = 0.5f * (g_x13[(2 * n + 1) * NF + f] + g_x13[(2 * n + 2) * NF + f]);
}
__global__ void k_prop_top() {
    for (int d = 8; d >= 0; d--) {
        int start = (1 << d) - 1, count = 1 << d, tot = count * NF;
        for (int i = threadIdx.x; i < tot; i += blockDim.x) {
            int n = start + i / NF, f = i % NF;
            g_x13[n * NF + f] = 0.5f * (g_x13[(2 * n + 1) * NF + f] + g_x13[(2 * n + 2) * NF + f]);
        }
        __syncthreads();
    }
}

// fp32 GEMM (only for K=13 node-MLP layer 1)
template <bool RELU>
__global__ void k_gemm(const float* __restrict__ A, const float* __restrict__ B,
                       const float* __restrict__ bias, float* __restrict__ C,
                       int M, int Nn, int K) {
    __shared__ float As[16][65];
    __shared__ float Bs[16][64];
    int tid = threadIdx.x;
    int tx = tid & 15, ty = tid >> 4;
    int rowBase = blockIdx.y * 64, colBase = blockIdx.x * 64;
    float acc[4][4];
#pragma unroll
    for (int i = 0; i < 4; i++)
#pragma unroll
        for (int j = 0; j < 4; j++) acc[i][j] = 0.f;
    for (int k0 = 0; k0 < K; k0 += 16) {
#pragma unroll
        for (int e = tid; e < 1024; e += 256) {
            int r = e >> 4, k = e & 15;
            int gr = rowBase + r, gk = k0 + k;
            As[k][r] = (gr < M && gk < K) ? A[(size_t)gr * K + gk] : 0.f;
        }
#pragma unroll
        for (int e = tid; e < 1024; e += 256) {
            int k = e >> 6, c = e & 63;
            int gk = k0 + k, gc = colBase + c;
            Bs[k][c] = (gk < K && gc < Nn) ? B[(size_t)gk * Nn + gc] : 0.f;
        }
        __syncthreads();
#pragma unroll
        for (int k = 0; k < 16; k++) {
            float a[4], b[4];
#pragma unroll
            for (int i = 0; i < 4; i++) a[i] = As[k][ty * 4 + i];
#pragma unroll
            for (int j = 0; j < 4; j++) b[j] = Bs[k][tx * 4 + j];
#pragma unroll
            for (int i = 0; i < 4; i++)
#pragma unroll
                for (int j = 0; j < 4; j++) acc[i][j] = fmaf(a[i], b[j], acc[i][j]);
        }
        __syncthreads();
    }
#pragma unroll
    for (int i = 0; i < 4; i++) {
        int r = rowBase + ty * 4 + i;
        if (r >= M) continue;
#pragma unroll
        for (int j = 0; j < 4; j++) {
            int c = colBase + tx * 4 + j;
            if (c >= Nn) continue;
            float v = acc[i][j] + (bias ? bias[c] : 0.f);
            if (RELU) v = fmaxf(v, 0.f);
            C[(size_t)r * Nn + c] = v;
        }
    }
}

// folded attention vectors: wsd[k][h]=sum_d W[k][h*128+d]*asrc[h][d]; [k][4+h] for adst
__global__ void k_wsd(const float* __restrict__ W, const float* __restrict__ as,
                      const float* __restrict__ ad) {
    int tid = threadIdx.x;           // 512 threads
    int k = tid >> 2, h = tid & 3;
    float s = 0.f, d2 = 0.f;
    const float* wr = W + (size_t)k * 512 + h * 128;
    const float* av = as + h * 128;
    const float* dv = ad + h * 128;
    for (int dd = 0; dd < 128; dd++) {
        float w = wr[dd];
        s  = fmaf(w, av[dd], s);
        d2 = fmaf(w, dv[dd], d2);
    }
    g_wsd[k * 8 + h]     = s;
    g_wsd[k * 8 + 4 + h] = d2;
}

// es/ed[n,h] = x[n,:] . wsd[:,h]   (warp per node)
__global__ void k_esed(const float* __restrict__ x) {
    int gw   = (blockIdx.x * blockDim.x + threadIdx.x) >> 5;
    int lane = threadIdx.x & 31;
    if (gw >= NNODES) return;
    const float* xr = x + (size_t)gw * HID;
    float a[8];
#pragma unroll
    for (int p = 0; p < 8; p++) a[p] = 0.f;
    for (int it = 0; it < 4; it++) {
        int k = lane + it * 32;
        float xv = xr[k];
        const float* w = g_wsd + k * 8;
#pragma unroll
        for (int p = 0; p < 8; p++) a[p] = fmaf(xv, w[p], a[p]);
    }
#pragma unroll
    for (int o = 16; o > 0; o >>= 1)
#pragma unroll
        for (int p = 0; p < 8; p++) a[p] += __shfl_xor_sync(0xffffffffu, a[p], o);
    if (lane == 0) {
#pragma unroll
        for (int h = 0; h < 4; h++) {
            g_es[gw * HEADS + h] = a[h];
            g_ed[gw * HEADS + h] = a[4 + h];
        }
    }
}

// fused GAT aggregate + mean-heads + bias + residual + LayerNorm (per-node block)
__global__ void k_gat(const float* __restrict__ xin, float* __restrict__ xout,
                      const float* __restrict__ gb, const float* __restrict__ lg,
                      const float* __restrict__ lb) {
    int n = blockIdx.x;
    int t = threadIdx.x;
    int lane = t & 31, wid = t >> 5;
    __shared__ float alpha[HEADS][4];
    __shared__ int   nbs[4];
    __shared__ int   scnt;
    __shared__ float ws1[4], ws2[4];
    if (t == 0) {
        int c = 0; int nb[4];
        nb[c++] = n;
        if (n > 0) nb[c++] = (n - 1) >> 1;
        int l = 2 * n + 1;
        if (l < NNODES) { nb[c++] = l; nb[c++] = l + 1; }
        scnt = c;
#pragma unroll
        for (int i = 0; i < 4; i++) nbs[i] = (i < c) ? nb[i] : n;
    }
    __syncthreads();
    int cnt = scnt;
    if (t < HEADS) {
        float edv = g_ed[n * HEADS + t];
        float e[4]; float m = -1e30f;
        for (int j = 0; j < cnt; j++) {
            float v = g_es[nbs[j] * HEADS + t] + edv;
            v = (v >= 0.f) ? v : 0.2f * v;
            e[j] = v; m = fmaxf(m, v);
        }
        float sum = 0.f;
        for (int j = 0; j < cnt; j++) { e[j] = expf(e[j] - m); sum += e[j]; }
        float inv = 1.f / sum;
#pragma unroll
        for (int j = 0; j < 4; j++) alpha[t][j] = (j < cnt) ? e[j] * inv : 0.f;
    }
    __syncthreads();
    float out = 0.f;
    for (int j = 0; j < cnt; j++) {
        const float* row = g_xp + (size_t)nbs[j] * (HEADS * HID);
#pragma unroll
        for (int h = 0; h < HEADS; h++) out = fmaf(alpha[h][j], row[h * HID + t], out);
    }
    float v = 0.25f * out + gb[t] + xin[(size_t)n * HID + t];
    float s = v;
#pragma unroll
    for (int o = 16; o > 0; o >>= 1) s += __shfl_xor_sync(0xffffffffu, s, o);
    if (lane == 0) ws1[wid] = s;
    __syncthreads();
    float mean = (ws1[0] + ws1[1] + ws1[2] + ws1[3]) * (1.f / HID);
    float dlt = v - mean;
    float s2 = dlt * dlt;
#pragma unroll
    for (int o = 16; o > 0; o >>= 1) s2 += __shfl_xor_sync(0xffffffffu, s2, o);
    if (lane == 0) ws2[wid] = s2;
    __syncthreads();
    float var = (ws2[0] + ws2[1] + ws2[2] + ws2[3]) * (1.f / HID);
    xout[(size_t)n * HID + t] = dlt * rsqrtf(var + 1e-5f) * lg[t] + lb[t];
}

// build edge bf16 matrix: Ae[e] = [Ah[e>>1] | Ah[e+1]]  (uint4 = 8 bf16)
__global__ void k_einb() {
    int i = blockIdx.x * blockDim.x + threadIdx.x;
    if (i >= NEDGE * 16) return;
    int e = i >> 4, q = i & 15;
    const uint4* Ah4 = (const uint4*)g_Ah;
    const uint4* Al4 = (const uint4*)g_Al;
    uint4* Aeh4 = (uint4*)g_Aeh;
    uint4* Ael4 = (uint4*)g_Ael;
    int s = e >> 1, d = e + 1;
    Aeh4[e * 32 + q]      = Ah4[s * 16 + q];
    Aeh4[e * 32 + 16 + q] = Ah4[d * 16 + q];
    Ael4[e * 32 + q]      = Al4[s * 16 + q];
    Ael4[e * 32 + 16 + q] = Al4[d * 16 + q];
}

// in-place bias add
__global__ void k_bias(float* __restrict__ x, const float* __restrict__ b, int n) {
    int i = blockIdx.x * blockDim.x + threadIdx.x;
    if (i < n) x[i] += b[i & (HID - 1)];
}
// dst = src + bias
__global__ void k_bias2(const float* __restrict__ src, const float* __restrict__ b,
                        float* __restrict__ dst, int n) {
    int i = blockIdx.x * blockDim.x + threadIdx.x;
    if (i < n) dst[i] = src[i] + b[i & (HID - 1)];
}
// edge MLP finish: x = relu(x + ef@W1c + b1)
__global__ void k_efb(float* __restrict__ x, const float* __restrict__ ef,
                      const float* __restrict__ W1c, const float* __restrict__ b1) {
    int i = blockIdx.x * blockDim.x + threadIdx.x;
    if (i >= NEDGE * HID) return;
    int e = i >> 7, c = i & 127;
    float v = x[i] + b1[c];
    const float* efr = ef + e * EFDIM;
#pragma unroll
    for (int j = 0; j < EFDIM; j++) v = fmaf(efr[j], W1c[j * HID + c], v);
    x[i] = fmaxf(v, 0.f);
}

// final head with fused bias+relu on input: logits = relu(H+b1) @ W(128x2) + b2
__global__ void k_out2(const float* __restrict__ H, const float* __restrict__ b1,
                       const float* __restrict__ W, const float* __restrict__ b2,
                       float* __restrict__ out) {
    int gw   = (blockIdx.x * blockDim.x + threadIdx.x) >> 5;
    int lane = threadIdx.x & 31;
    if (gw >= NEDGE) return;
    const float* h = H + (size_t)gw * HID;
    float s0 = 0.f, s1 = 0.f;
    for (int k = lane; k < HID; k += 32) {
        float hv = fmaxf(h[k] + b1[k], 0.f);
        s0 = fmaf(hv, W[k * 2], s0);
        s1 = fmaf(hv, W[k * 2 + 1], s1);
    }
#pragma unroll
    for (int o = 16; o > 0; o >>= 1) {
        s0 += __shfl_xor_sync(0xffffffffu, s0, o);
        s1 += __shfl_xor_sync(0xffffffffu, s1, o);
    }
    if (lane == 0) {
        out[(size_t)gw * 2]     = s0 + b2[0];
        out[(size_t)gw * 2 + 1] = s1 + b2[1];
    }
}

// ---------------- launch ----------------
extern "C" void kernel_launch(void* const* d_in, const int* in_sizes, int n_in,
                              void* d_out, int out_size) {
    const float* nf    = (const float*)d_in[0];
    const float* ef    = (const float*)d_in[2];
    const float* npW1  = (const float*)d_in[4];
    const float* npb1  = (const float*)d_in[5];
    const float* npW2  = (const float*)d_in[6];
    const float* npb2  = (const float*)d_in[7];
    const float* gatW  = (const float*)d_in[8];
    const float* gatAs = (const float*)d_in[9];
    const float* gatAd = (const float*)d_in[10];
    const float* gatB  = (const float*)d_in[11];
    const float* lnG   = (const float*)d_in[12];
    const float* lnB   = (const float*)d_in[13];
    const float* emW1  = (const float*)d_in[14];
    const float* emb1  = (const float*)d_in[15];
    const float* emW2  = (const float*)d_in[16];
    const float* emb2  = (const float*)d_in[17];
    const float* whW1  = (const float*)d_in[18];
    const float* whb1  = (const float*)d_in[19];
    const float* whW2  = (const float*)d_in[20];
    const float* whb2  = (const float*)d_in[21];

    float* out    = (float*)d_out;
    float* embOut = out + (size_t)NEDGE * 2;

    float *x13, *xA, *xB, *xp;
    __nv_bfloat16 *Ah, *Al, *Aeh, *Ael, *Bh, *Bl;
    cudaGetSymbolAddress((void**)&x13, g_x13);
    cudaGetSymbolAddress((void**)&xA,  g_xA);
    cudaGetSymbolAddress((void**)&xB,  g_xB);
    cudaGetSymbolAddress((void**)&xp,  g_xp);
    cudaGetSymbolAddress((void**)&Ah,  g_Ah);
    cudaGetSymbolAddress((void**)&Al,  g_Al);
    cudaGetSymbolAddress((void**)&Aeh, g_Aeh);
    cudaGetSymbolAddress((void**)&Ael, g_Ael);
    cudaGetSymbolAddress((void**)&Bh,  g_Bh);
    cudaGetSymbolAddress((void**)&Bl,  g_Bl);

    constexpr int SM128 = (2 * 128 * 136 + 2 * 128 * 136) * 2;  // 139264
    constexpr int SM256 = (2 * 128 * 136 + 2 * 256 * 136) * 2;  // 208896
    cudaFuncSetAttribute(k_mm<128, 1>, cudaFuncAttributeMaxDynamicSharedMemorySize, SM128);
    cudaFuncSetAttribute(k_mm<256, 1>, cudaFuncAttributeMaxDynamicSharedMemorySize, SM256);
    cudaFuncSetAttribute(k_mm<128, 2>, cudaFuncAttributeMaxDynamicSharedMemorySize, SM128);

    const int NE128 = NNODES * HID;   // node elems
    const int EE128 = NEDGE  * HID;   // edge elems

    // 1) propagate
    int n13 = NNODES * NF;
    k_copy<<<(n13 + 255) / 256, 256>>>(nf, x13, n13);
    for (int d = DEPTH - 1; d >= 9; d--) {
        int start = (1 << d) - 1, count = 1 << d;
        int tn = count * NF;
        k_prop<<<(tn + 255) / 256, 256>>>(start, count);
    }
    k_prop_top<<<1, 512>>>();

    // 2) node MLP
    dim3 gN(2, (NNODES + 63) / 64);
    k_gemm<true><<<gN, 256>>>(x13, npW1, npb1, xp, NNODES, HID, NF);     // H1 -> xp
    k_split <<<(NE128 + 255) / 256, 256>>>(xp, Ah, Al, NE128);
    k_splitT<<<(HID * HID + 255) / 256, 256>>>(npW2, Bh, Bl, HID, HID);
    k_mm<128, 1><<<dim3(512, 1), 256, SM128>>>(Ah, Al, Bh, Bl, xA, HID);
    k_bias  <<<(NE128 + 255) / 256, 256>>>(xA, npb2, NE128);

    // 3) GAT layers
    float* bufs[2] = {xA, xB};
    for (int l = 0; l < NL; l++) {
        float* xi = bufs[l & 1];
        float* xo = bufs[(l + 1) & 1];
        const float* Wl = gatW + (size_t)l * HID * HEADS * HID;
        k_split <<<(NE128 + 255) / 256, 256>>>(xi, Ah, Al, NE128);
        k_splitT<<<(HID * HEADS * HID + 255) / 256, 256>>>(Wl, Bh, Bl, HID, HEADS * HID);
        k_wsd   <<<1, 512>>>(Wl, gatAs + (size_t)l * HEADS * HID, gatAd + (size_t)l * HEADS * HID);
        k_esed  <<<(NNODES * 32 + 255) / 256, 256>>>(xi);
        k_mm<256, 1><<<dim3(512, 2), 256, SM256>>>(Ah, Al, Bh, Bl, xp, HEADS * HID);
        k_gat   <<<NNODES, HID>>>(xi, xo, gatB + l * HID, lnG + l * HID, lnB + l * HID);
    }
    float* xf = bufs[NL & 1];   // = xB

    // 4) edge MLP: [x_src|x_dst]@W1[0:256] (+ ef@W1c + b1, relu) -> H -> @W2+b2 = emb
    k_split <<<(NE128 + 255) / 256, 256>>>(xf, Ah, Al, NE128);
    k_einb  <<<(NEDGE * 16 + 255) / 256, 256>>>();
    k_splitT<<<(256 * HID + 255) / 256, 256>>>(emW1, Bh, Bl, 256, HID);
    k_mm<128, 2><<<dim3(512, 1), 256, SM128>>>(Aeh, Ael, Bh, Bl, xA, HID);
    k_efb   <<<(EE128 + 255) / 256, 256>>>(xA, ef, emW1 + 256 * HID, emb1);
    k_split <<<(EE128 + 255) / 256, 256>>>(xA, Ah, Al, EE128);
    k_splitT<<<(HID * HID + 255) / 256, 256>>>(emW2, Bh, Bl, HID, HID);
    k_mm<128, 1><<<dim3(512, 1), 256, SM128>>>(Ah, Al, Bh, Bl, xB, HID);
    k_bias2 <<<(EE128 + 255) / 256, 256>>>(xB, emb2, embOut, EE128);

    // 5) head: logits = relu(emb@whW1+b1)@whW2+b2
    k_split <<<(EE128 + 255) / 256, 256>>>(embOut, Ah, Al, EE128);
    k_splitT<<<(HID * HID + 255) / 256, 256>>>(whW1, Bh, Bl, HID, HID);
    k_mm<128, 1><<<dim3(512, 1), 256, SM128>>>(Ah, Al, Bh, Bl, xA, HID);
    k_out2  <<<(NEDGE * 32 + 255) / 256, 256>>>(xA, whb1, whW2, whb2, out);
}